// round 13
// baseline (speedup 1.0000x reference)
#include <cuda_runtime.h>
#include <stdint.h>

#define BATCH   4
#define NPTS    100000
#define TOTAL   (BATCH * NPTS)
#define D_IN    16
#define D_TOT   19
#define MLP_N   128
#define GRID_X  468
#define GRID_Y  468
#define VOL     (GRID_X * GRID_Y)
#define NVOX    (BATCH * VOL)        // 876096 = 27378 * 32
#define NCHUNK  (NVOX / 32)          // 27378
#define CAP     16
#define NSLICE  8
#define FULLM   0xffffffffu
#define VOX_BYTES 512

__device__ int d_cnt[NVOX];                 // per-voxel count (self-zeroing in fill)
__device__ int d_pidx[(size_t)NVOX * CAP];  // per-voxel point indices

// ---- packed f32x2 helpers (FFMA2, PTX-only) ----
__device__ __forceinline__ unsigned long long dup2(float v) {
    unsigned long long r;
    asm("mov.b64 %0, {%1, %1};" : "=l"(r) : "f"(v));
    return r;
}
__device__ __forceinline__ unsigned long long fma2(unsigned long long a,
                                                   unsigned long long b,
                                                   unsigned long long c) {
    unsigned long long d;
    asm("fma.rn.f32x2 %0, %1, %2, %3;" : "=l"(d) : "l"(a), "l"(b), "l"(c));
    return d;
}
__device__ __forceinline__ void unpack2(unsigned long long p, float& lo, float& hi) {
    asm("mov.b64 {%0, %1}, %2;" : "=f"(lo), "=f"(hi) : "l"(p));
}
__device__ __forceinline__ unsigned long long pack2(float lo, float hi) {
    unsigned long long r;
    asm("mov.b64 %0, {%1, %2};" : "=l"(r) : "f"(lo), "f"(hi));
    return r;
}

// ---- K2: bin valid points (per-voxel atomics only) ----
__global__ void __launch_bounds__(256)
bin_points_kernel(const float* __restrict__ xyz,
                  const unsigned int* __restrict__ mask)
{
    const int p = blockIdx.x * blockDim.x + threadIdx.x;
    if (p >= TOTAL) return;
    if (mask[p] == 0u) return;

    const float x = xyz[p * 3 + 0];
    const float y = xyz[p * 3 + 1];
    const float z = xyz[p * 3 + 2];
    const int ivx = (int)floorf(x / 0.32f) + 234;
    const int ivy = (int)floorf(y / 0.32f) + 234;
    const int ivz = (int)floorf(z / 6.0f) + 1;
    if (ivx < 0 || ivx >= GRID_X || ivy < 0 || ivy >= GRID_Y || ivz != 0) return;

    const int batch = p / NPTS;
    const int vid = batch * VOL + ivx * GRID_X + ivy;
    const int slot = atomicAdd(&d_cnt[vid], 1);
    if (slot < CAP) d_pidx[(size_t)vid * CAP + slot] = p;
}

// ---- fill: one warp per 32-voxel chunk; writes ONLY occupied voxels ----
// (empties were zeroed by the memset slice this launch depends on)
__global__ void __launch_bounds__(256)
fill_kernel(const float* __restrict__ xyz,
            const float* __restrict__ pfeat,
            const float* __restrict__ W,
            const float* __restrict__ bias,
            float* __restrict__ out,
            int chunk_lo, int chunk_hi)
{
    __shared__ float4 sW4[D_TOT * (MLP_N / 4)];   // 9728 B (L2-hot after block 0)
    for (int i = threadIdx.x; i < D_TOT * (MLP_N / 4); i += 256)
        sW4[i] = ((const float4*)W)[i];
    __syncthreads();

    const int lane = threadIdx.x & 31;
    const int cidx = chunk_lo + ((blockIdx.x * 256 + threadIdx.x) >> 5);
    if (cidx >= chunk_hi) return;                 // warp-uniform
    const int base = cidx * 32;

    const int c = d_cnt[base + lane];
    d_cnt[base + lane] = 0;                       // reset for next replay
    const unsigned om_all = __ballot_sync(FULLM, c > 0);
    if (!om_all) return;                          // fully empty chunk

    // lane-parallel first-point indices for all occupied voxels in the chunk
    const int p0 = (c > 0) ? __ldg(&d_pidx[(size_t)(base + lane) * CAP]) : 0;

    const float4 b4 = __ldg(((const float4*)bias) + lane);
    const unsigned long long b01 = pack2(b4.x, b4.y);
    const unsigned long long b23 = pack2(b4.z, b4.w);

    unsigned om = om_all;
    while (om) {
        const int i = __ffs(om) - 1;
        om &= om - 1;
        const int ci = __shfl_sync(FULLM, c, i);
        const int v  = base + i;
        const int npt = ci < CAP ? ci : CAP;

        unsigned long long vmax01 = pack2(-1e30f, -1e30f);
        unsigned long long vmax23 = vmax01;

        for (int k = 0; k < npt; ++k) {
            const int pt = (k == 0) ? __shfl_sync(FULLM, p0, i)
                                    : __ldg(&d_pidx[(size_t)v * CAP + k]);
            const float x = xyz[pt * 3 + 0];
            const float y = xyz[pt * 3 + 1];
            const float z = xyz[pt * 3 + 2];
            const float dx = x - floorf(x / 0.32f) * 0.32f;
            const float dy = y - floorf(y / 0.32f) * 0.32f;
            const float dz = z - floorf(z / 6.0f) * 6.0f;

            const float4* f4 = (const float4*)(pfeat + (size_t)pt * D_IN);
            const float4 fa = f4[0], fb = f4[1], fc = f4[2], fd = f4[3];
            const float vin[D_TOT] = {
                fa.x, fa.y, fa.z, fa.w,
                fb.x, fb.y, fb.z, fb.w,
                fc.x, fc.y, fc.z, fc.w,
                fd.x, fd.y, fd.z, fd.w,
                dx, dy, dz
            };
            unsigned long long acc01 = b01, acc23 = b23;
            #pragma unroll
            for (int d = 0; d < D_TOT; ++d) {
                const ulonglong2 wp =
                    *(const ulonglong2*)(sW4 + d * (MLP_N / 4) + lane);
                const unsigned long long vv = dup2(vin[d]);
                acc01 = fma2(vv, wp.x, acc01);
                acc23 = fma2(vv, wp.y, acc23);
            }
            float a0, a1, a2, a3, m0, m1, m2, m3;
            unpack2(acc01, a0, a1); unpack2(acc23, a2, a3);
            unpack2(vmax01, m0, m1); unpack2(vmax23, m2, m3);
            vmax01 = pack2(fmaxf(m0, a0), fmaxf(m1, a1));
            vmax23 = pack2(fmaxf(m2, a2), fmaxf(m3, a3));
        }

        float m0, m1, m2, m3;
        unpack2(vmax01, m0, m1);
        unpack2(vmax23, m2, m3);
        // relu monotone: max-then-relu == max-of-relus
        __stcs(((float4*)(out + (size_t)v * MLP_N)) + lane,
               make_float4(fmaxf(m0, 0.f), fmaxf(m1, 0.f),
                           fmaxf(m2, 0.f), fmaxf(m3, 0.f)));
    }
}

extern "C" void kernel_launch(void* const* d_in, const int* in_sizes, int n_in,
                              void* d_out, int out_size)
{
    const float*        xyz   = (const float*)d_in[0];
    const float*        pfeat = (const float*)d_in[1];
    const unsigned int* mask  = (const unsigned int*)d_in[2];
    const float*        W     = (const float*)d_in[3];
    const float*        bias  = (const float*)d_in[4];
    float*              out   = (float*)d_out;

    // One-time host-object setup (no device memory involved).
    static cudaStream_t s1 = nullptr;
    static cudaEvent_t evFork = nullptr, evJoin = nullptr, evM[NSLICE];
    if (!s1) {
        cudaStreamCreateWithFlags(&s1, cudaStreamNonBlocking);
        cudaEventCreateWithFlags(&evFork, cudaEventDisableTiming);
        cudaEventCreateWithFlags(&evJoin, cudaEventDisableTiming);
        for (int i = 0; i < NSLICE; ++i)
            cudaEventCreateWithFlags(&evM[i], cudaEventDisableTiming);
    }

    // Fork: memset slices run on s1, overlapping bin + earlier fills on stream 0.
    cudaEventRecord(evFork, 0);
    cudaStreamWaitEvent(s1, evFork, 0);

    int lo[NSLICE + 1];
    for (int i = 0; i <= NSLICE; ++i) lo[i] = (int)((long long)i * NCHUNK / NSLICE);

    for (int i = 0; i < NSLICE; ++i) {
        char* base = (char*)out + (size_t)lo[i] * 32 * VOX_BYTES;
        const size_t bytes = (size_t)(lo[i + 1] - lo[i]) * 32 * VOX_BYTES;
        cudaMemsetAsync(base, 0, bytes, s1);
        cudaEventRecord(evM[i], s1);
    }

    // Bin on stream 0 (doesn't touch out) — overlaps the first memset slices.
    bin_points_kernel<<<(TOTAL + 255) / 256, 256>>>(xyz, mask);

    // Fill slice i only after its memset slice completed.
    for (int i = 0; i < NSLICE; ++i) {
        cudaStreamWaitEvent(0, evM[i], 0);
        const int nchunks = lo[i + 1] - lo[i];
        const int blocks = (nchunks * 32 + 255) / 256;   // one warp per chunk
        fill_kernel<<<blocks, 256>>>(xyz, pfeat, W, bias, out, lo[i], lo[i + 1]);
    }

    // Join s1 back into stream 0 (fills already depend on all memsets, but be explicit).
    cudaEventRecord(evJoin, s1);
    cudaStreamWaitEvent(0, evJoin, 0);
}

// round 14
// speedup vs baseline: 1.6378x; 1.6378x over previous
#include <cuda_runtime.h>
#include <stdint.h>

#define BATCH   4
#define NPTS    100000
#define TOTAL   (BATCH * NPTS)
#define D_IN    16
#define D_TOT   19
#define MLP_N   128
#define GRID_X  468
#define GRID_Y  468
#define VOL     (GRID_X * GRID_Y)
#define NVOX    (BATCH * VOL)        // 876096 = 27378 * 32
#define NCHUNK  (NVOX / 32)          // 27378
#define CAP     16
#define FULLM   0xffffffffu

#define THREADS 256
#define BLOCKS  740                  // 5 resident blocks/SM
#define FILL_BLOCKS  296             // 2 of every 5
#define SWEEP_BLOCKS 444             // 3 of every 5
#define FILL_WARPS   (FILL_BLOCKS * 8)
#define SWEEP_WARPS  (SWEEP_BLOCKS * 8)

__device__ int           d_cnt[NVOX];                 // fill's copy (fill zeroes it)
__device__ unsigned char d_flag[NVOX];                // sweep's copy (sweep zeroes it)
__device__ int           d_pidx[(size_t)NVOX * CAP];

// ---- packed f32x2 helpers (FFMA2, PTX-only) ----
__device__ __forceinline__ unsigned long long dup2(float v) {
    unsigned long long r;
    asm("mov.b64 %0, {%1, %1};" : "=l"(r) : "f"(v));
    return r;
}
__device__ __forceinline__ unsigned long long fma2(unsigned long long a,
                                                   unsigned long long b,
                                                   unsigned long long c) {
    unsigned long long d;
    asm("fma.rn.f32x2 %0, %1, %2, %3;" : "=l"(d) : "l"(a), "l"(b), "l"(c));
    return d;
}
__device__ __forceinline__ void unpack2(unsigned long long p, float& lo, float& hi) {
    asm("mov.b64 {%0, %1}, %2;" : "=f"(lo), "=f"(hi) : "l"(p));
}
__device__ __forceinline__ unsigned long long pack2(float lo, float hi) {
    unsigned long long r;
    asm("mov.b64 %0, {%1, %2};" : "=l"(r) : "f"(lo), "f"(hi));
    return r;
}
__device__ __forceinline__ void prefetchL1(const void* ptr) {
    asm volatile("prefetch.global.L1 [%0];" :: "l"(ptr));
}

// ---- K2: bin valid points; write both occupancy copies ----
__global__ void __launch_bounds__(256)
bin_points_kernel(const float* __restrict__ xyz,
                  const unsigned int* __restrict__ mask)
{
    const int p = blockIdx.x * blockDim.x + threadIdx.x;
    if (p >= TOTAL) return;
    if (mask[p] == 0u) return;

    const float x = xyz[p * 3 + 0];
    const float y = xyz[p * 3 + 1];
    const float z = xyz[p * 3 + 2];
    const int ivx = (int)floorf(x / 0.32f) + 234;
    const int ivy = (int)floorf(y / 0.32f) + 234;
    const int ivz = (int)floorf(z / 6.0f) + 1;
    if (ivx < 0 || ivx >= GRID_X || ivy < 0 || ivy >= GRID_Y || ivz != 0) return;

    const int batch = p / NPTS;
    const int vid = batch * VOL + ivx * GRID_X + ivy;
    const int slot = atomicAdd(&d_cnt[vid], 1);
    if (slot < CAP) d_pidx[(size_t)vid * CAP + slot] = p;
    d_flag[vid] = 1;    // plain store; duplicates benign (sweep's occupancy copy)
}

// ---- fill role: occupied voxels only; owns & zeroes d_cnt ----
__device__ void fill_role(int fwarp, int lane,
                          const float* __restrict__ xyz,
                          const float* __restrict__ pfeat,
                          const float4* __restrict__ sW4,
                          const float* __restrict__ bias,
                          float* __restrict__ out)
{
    const float4 b4 = __ldg(((const float4*)bias) + lane);
    const unsigned long long b01 = pack2(b4.x, b4.y);
    const unsigned long long b23 = pack2(b4.z, b4.w);

    for (int cidx = fwarp; cidx < NCHUNK; cidx += FILL_WARPS) {
        const int base = cidx * 32;
        const int c = d_cnt[base + lane];
        const unsigned om_all = __ballot_sync(FULLM, c > 0);
        if (!om_all) continue;
        d_cnt[base + lane] = 0;    // reset for next replay (exclusive owner)

        // lane-parallel first-point index + L1 warm for all occupied voxels
        const int p0 = (c > 0) ? __ldg(&d_pidx[(size_t)(base + lane) * CAP]) : 0;
        if (c > 0) {
            prefetchL1(xyz + (size_t)p0 * 3);
            prefetchL1(pfeat + (size_t)p0 * D_IN);
        }

        unsigned om = om_all;
        while (om) {
            const int i = __ffs(om) - 1;
            om &= om - 1;
            const int ci = __shfl_sync(FULLM, c, i);
            const int v  = base + i;
            const int npt = ci < CAP ? ci : CAP;

            unsigned long long vmax01 = pack2(-1e30f, -1e30f);
            unsigned long long vmax23 = vmax01;

            for (int k = 0; k < npt; ++k) {
                const int pt = (k == 0) ? __shfl_sync(FULLM, p0, i)
                                        : __ldg(&d_pidx[(size_t)v * CAP + k]);
                const float x = xyz[pt * 3 + 0];
                const float y = xyz[pt * 3 + 1];
                const float z = xyz[pt * 3 + 2];
                const float dx = x - floorf(x / 0.32f) * 0.32f;
                const float dy = y - floorf(y / 0.32f) * 0.32f;
                const float dz = z - floorf(z / 6.0f) * 6.0f;

                const float4* f4 = (const float4*)(pfeat + (size_t)pt * D_IN);
                const float4 fa = f4[0], fb = f4[1], fc = f4[2], fd = f4[3];
                const float vin[D_TOT] = {
                    fa.x, fa.y, fa.z, fa.w,
                    fb.x, fb.y, fb.z, fb.w,
                    fc.x, fc.y, fc.z, fc.w,
                    fd.x, fd.y, fd.z, fd.w,
                    dx, dy, dz
                };
                unsigned long long acc01 = b01, acc23 = b23;
                #pragma unroll
                for (int d = 0; d < D_TOT; ++d) {
                    const ulonglong2 wp =
                        *(const ulonglong2*)(sW4 + d * (MLP_N / 4) + lane);
                    const unsigned long long vv = dup2(vin[d]);
                    acc01 = fma2(vv, wp.x, acc01);
                    acc23 = fma2(vv, wp.y, acc23);
                }
                float a0, a1, a2, a3, m0, m1, m2, m3;
                unpack2(acc01, a0, a1); unpack2(acc23, a2, a3);
                unpack2(vmax01, m0, m1); unpack2(vmax23, m2, m3);
                vmax01 = pack2(fmaxf(m0, a0), fmaxf(m1, a1));
                vmax23 = pack2(fmaxf(m2, a2), fmaxf(m3, a3));
            }

            float m0, m1, m2, m3;
            unpack2(vmax01, m0, m1);
            unpack2(vmax23, m2, m3);
            // relu monotone: max-then-relu == max-of-relus
            __stcs(((float4*)(out + (size_t)v * MLP_N)) + lane,
                   make_float4(fmaxf(m0, 0.f), fmaxf(m1, 0.f),
                               fmaxf(m2, 0.f), fmaxf(m3, 0.f)));
        }
    }
}

// ---- sweep role: empty voxels only; owns & zeroes d_flag; no load chains ----
__device__ void sweep_role(int swarp, int lane, float* __restrict__ out)
{
    const float4 z4 = make_float4(0.f, 0.f, 0.f, 0.f);

    int cidx = swarp;
    unsigned char f = (cidx < NCHUNK) ? d_flag[cidx * 32 + lane] : 1;

    for (; cidx < NCHUNK; cidx += SWEEP_WARPS) {
        const int nxt = cidx + SWEEP_WARPS;
        const unsigned char fn = (nxt < NCHUNK) ? d_flag[nxt * 32 + lane] : 1;  // prefetch

        const int base = cidx * 32;
        d_flag[base + lane] = 0;    // reset for next replay (exclusive owner)

        unsigned em = __ballot_sync(FULLM, f == 0);   // empty voxels
        while (em) {
            const int i = __ffs(em) - 1;
            em &= em - 1;
            __stcs(((float4*)(out + (size_t)(base + i) * MLP_N)) + lane, z4);
        }
        f = fn;
    }
}

// ---- K3: warp-specialized single launch; disjoint writes ----
__global__ void __launch_bounds__(THREADS, 5)
output_kernel(const float* __restrict__ xyz,
              const float* __restrict__ pfeat,
              const float* __restrict__ W,
              const float* __restrict__ bias,
              float* __restrict__ out)
{
    __shared__ float4 sW4[D_TOT * (MLP_N / 4)];   // 9728 B
    for (int i = threadIdx.x; i < D_TOT * (MLP_N / 4); i += THREADS)
        sW4[i] = ((const float4*)W)[i];
    __syncthreads();

    const int lane = threadIdx.x & 31;
    const int widb = threadIdx.x >> 5;
    const int grp  = blockIdx.x / 5;
    const int sub  = blockIdx.x % 5;

    if (sub < 2)
        fill_role((grp * 2 + sub) * 8 + widb, lane, xyz, pfeat, sW4, bias, out);
    else
        sweep_role((grp * 3 + (sub - 2)) * 8 + widb, lane, out);
}

extern "C" void kernel_launch(void* const* d_in, const int* in_sizes, int n_in,
                              void* d_out, int out_size)
{
    const float*        xyz   = (const float*)d_in[0];
    const float*        pfeat = (const float*)d_in[1];
    const unsigned int* mask  = (const unsigned int*)d_in[2];
    const float*        W     = (const float*)d_in[3];
    const float*        bias  = (const float*)d_in[4];
    float*              out   = (float*)d_out;

    // d_cnt / d_flag start zeroed (static init) and self-zero each call.
    bin_points_kernel<<<(TOTAL + 255) / 256, 256>>>(xyz, mask);
    output_kernel<<<BLOCKS, THREADS>>>(xyz, pfeat, W, bias, out);
}

// round 15
// speedup vs baseline: 2.2798x; 1.3920x over previous
#include <cuda_runtime.h>
#include <stdint.h>

#define BATCH   4
#define NPTS    100000
#define TOTAL   (BATCH * NPTS)
#define D_IN    16
#define D_TOT   19
#define MLP_N   128
#define GRID_X  468
#define GRID_Y  468
#define VOL     (GRID_X * GRID_Y)
#define NVOX    (BATCH * VOL)        // 876096 = 27378 * 32
#define CAP     16

#define THREADS 256
#define BLOCKS  740                  // persistent: 5 blocks/SM * 148
#define NWARPS  (BLOCKS * THREADS / 32)
#define STRIDE  (NWARPS * 32)

__device__ int d_cnt[NVOX];                 // per-voxel point count (self-zeroing)
__device__ int d_pidx[(size_t)NVOX * CAP];  // per-voxel point indices

// ---- packed f32x2 helpers (FFMA2, PTX-only) ----
__device__ __forceinline__ unsigned long long dup2(float v) {
    unsigned long long r;
    asm("mov.b64 %0, {%1, %1};" : "=l"(r) : "f"(v));
    return r;
}
__device__ __forceinline__ unsigned long long fma2(unsigned long long a,
                                                   unsigned long long b,
                                                   unsigned long long c) {
    unsigned long long d;
    asm("fma.rn.f32x2 %0, %1, %2, %3;" : "=l"(d) : "l"(a), "l"(b), "l"(c));
    return d;
}
__device__ __forceinline__ void unpack2(unsigned long long p, float& lo, float& hi) {
    asm("mov.b64 {%0, %1}, %2;" : "=f"(lo), "=f"(hi) : "l"(p));
}
__device__ __forceinline__ unsigned long long pack2(float lo, float hi) {
    unsigned long long r;
    asm("mov.b64 %0, {%1, %2};" : "=l"(r) : "f"(lo), "f"(hi));
    return r;
}
__device__ __forceinline__ void prefetchL1(const void* ptr) {
    asm volatile("prefetch.global.L1 [%0];" :: "l"(ptr));
}
// write-through streaming store: no L2 dirty-line establishment
__device__ __forceinline__ void stwt4(float4* dst, float4 v) {
    asm volatile("st.global.wt.v4.f32 [%0], {%1, %2, %3, %4};"
                 :: "l"(dst), "f"(v.x), "f"(v.y), "f"(v.z), "f"(v.w) : "memory");
}

// ---- K2: bin valid points (per-voxel atomics only) ----
__global__ void __launch_bounds__(256)
bin_points_kernel(const float* __restrict__ xyz,
                  const unsigned int* __restrict__ mask)
{
    const int p = blockIdx.x * blockDim.x + threadIdx.x;
    if (p >= TOTAL) return;
    if (mask[p] == 0u) return;

    const float x = xyz[p * 3 + 0];
    const float y = xyz[p * 3 + 1];
    const float z = xyz[p * 3 + 2];
    const int ivx = (int)floorf(x / 0.32f) + 234;
    const int ivy = (int)floorf(y / 0.32f) + 234;
    const int ivz = (int)floorf(z / 6.0f) + 1;
    if (ivx < 0 || ivx >= GRID_X || ivy < 0 || ivy >= GRID_Y || ivz != 0) return;

    const int batch = p / NPTS;
    const int vid = batch * VOL + ivx * GRID_X + ivy;
    const int slot = atomicAdd(&d_cnt[vid], 1);
    if (slot < CAP) d_pidx[(size_t)vid * CAP + slot] = p;
}

// ---- K3: fused gather (R9 structure); stores are write-through ----
__global__ void __launch_bounds__(THREADS, 5)
gather_kernel(const float* __restrict__ xyz,
              const float* __restrict__ pfeat,
              const float* __restrict__ W,
              const float* __restrict__ bias,
              float* __restrict__ out)
{
    __shared__ float4 sW4[D_TOT * (MLP_N / 4)];   // 9728 B, rows = packed f32x2 pairs
    for (int i = threadIdx.x; i < D_TOT * (MLP_N / 4); i += THREADS)
        sW4[i] = ((const float4*)W)[i];
    __syncthreads();

    const int lane  = threadIdx.x & 31;
    const int gwarp = (blockIdx.x * THREADS + threadIdx.x) >> 5;

    const float4 b4 = __ldg(((const float4*)bias) + lane);
    const unsigned long long b01 = pack2(b4.x, b4.y);
    const unsigned long long b23 = pack2(b4.z, b4.w);
    const float4 zero4 = make_float4(0.f, 0.f, 0.f, 0.f);

    int chunk = gwarp * 32;

    // Pipeline: counts 2 chunks deep, first-pidx 1 chunk deep (lane-parallel).
    int c = 0, c1 = 0, p = 0;
    if (chunk < NVOX) {
        c = __ldg(&d_cnt[chunk + lane]);
        p = (c > 0) ? __ldg(&d_pidx[(size_t)(chunk + lane) * CAP]) : 0;
        if (c > 0) {
            prefetchL1(xyz + (size_t)p * 3);
            prefetchL1(pfeat + (size_t)p * D_IN);
        }
    }
    if (chunk + STRIDE < NVOX) c1 = __ldg(&d_cnt[chunk + STRIDE + lane]);

    for (; chunk < NVOX; chunk += STRIDE) {
        const int nxt  = chunk + STRIDE;
        const int nxt2 = chunk + 2 * STRIDE;
        const int c2 = (nxt2 < NVOX) ? __ldg(&d_cnt[nxt2 + lane]) : 0;
        int p1 = 0;
        if (nxt < NVOX && c1 > 0)
            p1 = __ldg(&d_pidx[(size_t)(nxt + lane) * CAP]);

        d_cnt[chunk + lane] = 0;          // reset for the next replay (exclusive owner)

        #pragma unroll 4
        for (int i = 0; i < 32; ++i) {
            const int ci = __shfl_sync(0xffffffffu, c, i);
            const int v  = chunk + i;
            float4* dst = ((float4*)(out + (size_t)v * MLP_N)) + lane;
            if (ci == 0) {                       // warp-uniform
                stwt4(dst, zero4);               // write-through zero
                continue;
            }
            const int npt = ci < CAP ? ci : CAP;
            unsigned long long vmax01 = pack2(-1e30f, -1e30f);
            unsigned long long vmax23 = vmax01;

            for (int k = 0; k < npt; ++k) {
                const int pt = (k == 0) ? __shfl_sync(0xffffffffu, p, i)
                                        : __ldg(&d_pidx[(size_t)v * CAP + k]);
                const float x = xyz[pt * 3 + 0];
                const float y = xyz[pt * 3 + 1];
                const float z = xyz[pt * 3 + 2];
                const float dx = x - floorf(x / 0.32f) * 0.32f;
                const float dy = y - floorf(y / 0.32f) * 0.32f;
                const float dz = z - floorf(z / 6.0f) * 6.0f;

                const float4* f4 = (const float4*)(pfeat + (size_t)pt * D_IN);
                const float4 fa = f4[0], fb = f4[1], fc = f4[2], fd = f4[3];
                const float vin[D_TOT] = {
                    fa.x, fa.y, fa.z, fa.w,
                    fb.x, fb.y, fb.z, fb.w,
                    fc.x, fc.y, fc.z, fc.w,
                    fd.x, fd.y, fd.z, fd.w,
                    dx, dy, dz
                };
                unsigned long long acc01 = b01, acc23 = b23;
                #pragma unroll
                for (int d = 0; d < D_TOT; ++d) {
                    const ulonglong2 wp =
                        *(const ulonglong2*)(sW4 + d * (MLP_N / 4) + lane);
                    const unsigned long long vv = dup2(vin[d]);
                    acc01 = fma2(vv, wp.x, acc01);
                    acc23 = fma2(vv, wp.y, acc23);
                }
                float a0, a1, a2, a3, m0, m1, m2, m3;
                unpack2(acc01, a0, a1); unpack2(acc23, a2, a3);
                unpack2(vmax01, m0, m1); unpack2(vmax23, m2, m3);
                vmax01 = pack2(fmaxf(m0, a0), fmaxf(m1, a1));
                vmax23 = pack2(fmaxf(m2, a2), fmaxf(m3, a3));
            }

            float m0, m1, m2, m3;
            unpack2(vmax01, m0, m1);
            unpack2(vmax23, m2, m3);
            // relu monotone: max-then-relu == max-of-relus
            stwt4(dst, make_float4(fmaxf(m0, 0.f), fmaxf(m1, 0.f),
                                   fmaxf(m2, 0.f), fmaxf(m3, 0.f)));
        }

        // p1 has landed by now (issued ~700 cyc ago): warm L1 for next chunk.
        if (c1 > 0) {
            prefetchL1(xyz + (size_t)p1 * 3);
            prefetchL1(pfeat + (size_t)p1 * D_IN);
        }
        c = c1; c1 = c2; p = p1;
    }
}

extern "C" void kernel_launch(void* const* d_in, const int* in_sizes, int n_in,
                              void* d_out, int out_size)
{
    const float*        xyz   = (const float*)d_in[0];
    const float*        pfeat = (const float*)d_in[1];
    const unsigned int* mask  = (const unsigned int*)d_in[2];
    const float*        W     = (const float*)d_in[3];
    const float*        bias  = (const float*)d_in[4];
    float*              out   = (float*)d_out;

    // d_cnt starts zeroed (static init) and is re-zeroed by gather_kernel each call.
    bin_points_kernel<<<(TOTAL + 255) / 256, 256>>>(xyz, mask);
    gather_kernel<<<BLOCKS, THREADS>>>(xyz, pfeat, W, bias, out);
}

// round 16
// speedup vs baseline: 2.6372x; 1.1568x over previous
#include <cuda_runtime.h>
#include <stdint.h>

#define BATCH   4
#define NPTS    100000
#define TOTAL   (BATCH * NPTS)
#define D_IN    16
#define D_TOT   19
#define MLP_N   128
#define GRID_X  468
#define GRID_Y  468
#define VOL     (GRID_X * GRID_Y)
#define NVOX    (BATCH * VOL)        // 876096 = 27378 * 32
#define CAP     16

#define THREADS 256
#define BLOCKS  740                  // persistent: 5 blocks/SM * 148
#define NWARPS  (BLOCKS * THREADS / 32)
#define STRIDE  (NWARPS * 32)
#define FULLM   0xffffffffu

__device__ int d_cnt[NVOX];                 // per-voxel point count (self-zeroing)
__device__ int d_pidx[(size_t)NVOX * CAP];  // per-voxel point indices

// ---- packed f32x2 helpers (FFMA2, PTX-only) ----
__device__ __forceinline__ unsigned long long dup2(float v) {
    unsigned long long r;
    asm("mov.b64 %0, {%1, %1};" : "=l"(r) : "f"(v));
    return r;
}
__device__ __forceinline__ unsigned long long fma2(unsigned long long a,
                                                   unsigned long long b,
                                                   unsigned long long c) {
    unsigned long long d;
    asm("fma.rn.f32x2 %0, %1, %2, %3;" : "=l"(d) : "l"(a), "l"(b), "l"(c));
    return d;
}
__device__ __forceinline__ void unpack2(unsigned long long p, float& lo, float& hi) {
    asm("mov.b64 {%0, %1}, %2;" : "=f"(lo), "=f"(hi) : "l"(p));
}
__device__ __forceinline__ unsigned long long pack2(float lo, float hi) {
    unsigned long long r;
    asm("mov.b64 %0, {%1, %2};" : "=l"(r) : "f"(lo), "f"(hi));
    return r;
}
__device__ __forceinline__ void prefetchL1(const void* ptr) {
    asm volatile("prefetch.global.L1 [%0];" :: "l"(ptr));
}

// ---- K2: bin valid points (per-voxel atomics only) ----
__global__ void __launch_bounds__(256)
bin_points_kernel(const float* __restrict__ xyz,
                  const unsigned int* __restrict__ mask)
{
    const int p = blockIdx.x * blockDim.x + threadIdx.x;
    if (p >= TOTAL) return;
    if (mask[p] == 0u) return;

    const float x = xyz[p * 3 + 0];
    const float y = xyz[p * 3 + 1];
    const float z = xyz[p * 3 + 2];
    const int ivx = (int)floorf(x / 0.32f) + 234;
    const int ivy = (int)floorf(y / 0.32f) + 234;
    const int ivz = (int)floorf(z / 6.0f) + 1;
    if (ivx < 0 || ivx >= GRID_X || ivy < 0 || ivy >= GRID_Y || ivz != 0) return;

    const int batch = p / NPTS;
    const int vid = batch * VOL + ivx * GRID_X + ivy;
    const int slot = atomicAdd(&d_cnt[vid], 1);
    if (slot < CAP) d_pidx[(size_t)vid * CAP + slot] = p;
}

// ---- K3: fused gather (R9 structure); data prefetch issued with real lead ----
__global__ void __launch_bounds__(THREADS, 5)
gather_kernel(const float* __restrict__ xyz,
              const float* __restrict__ pfeat,
              const float* __restrict__ W,
              const float* __restrict__ bias,
              float* __restrict__ out)
{
    __shared__ float4 sW4[D_TOT * (MLP_N / 4)];   // 9728 B, rows = packed f32x2 pairs
    for (int i = threadIdx.x; i < D_TOT * (MLP_N / 4); i += THREADS)
        sW4[i] = ((const float4*)W)[i];
    __syncthreads();

    const int lane  = threadIdx.x & 31;
    const int gwarp = (blockIdx.x * THREADS + threadIdx.x) >> 5;

    const float4 b4 = __ldg(((const float4*)bias) + lane);
    const unsigned long long b01 = pack2(b4.x, b4.y);
    const unsigned long long b23 = pack2(b4.z, b4.w);
    const float4 zero4 = make_float4(0.f, 0.f, 0.f, 0.f);

    int chunk = gwarp * 32;

    // Pipeline: counts 2 chunks deep, first-pidx 1 chunk deep (lane-parallel).
    int c = 0, c1 = 0, p = 0;
    if (chunk < NVOX) {
        c = __ldg(&d_cnt[chunk + lane]);
        p = (c > 0) ? __ldg(&d_pidx[(size_t)(chunk + lane) * CAP]) : 0;
        if (c > 0) {
            prefetchL1(xyz + (size_t)p * 3);
            prefetchL1(pfeat + (size_t)p * D_IN);
        }
    }
    if (chunk + STRIDE < NVOX) c1 = __ldg(&d_cnt[chunk + STRIDE + lane]);

    for (; chunk < NVOX; chunk += STRIDE) {
        const int nxt  = chunk + STRIDE;
        const int nxt2 = chunk + 2 * STRIDE;
        const int c2 = (nxt2 < NVOX) ? __ldg(&d_cnt[nxt2 + lane]) : 0;
        int p1 = 0;
        if (nxt < NVOX && c1 > 0)
            p1 = __ldg(&d_pidx[(size_t)(nxt + lane) * CAP]);

        d_cnt[chunk + lane] = 0;          // reset for the next replay (exclusive owner)

        // Two halves: issue next-chunk data prefetch between them so it gets
        // ~half a chunk (~500 cyc) of lead time before use (R9 had ~0 lead).
        #pragma unroll
        for (int half = 0; half < 2; ++half) {
            #pragma unroll 4
            for (int ii = 0; ii < 16; ++ii) {
                const int i = half * 16 + ii;
                const int ci = __shfl_sync(FULLM, c, i);
                const int v  = chunk + i;
                float4* dst = ((float4*)(out + (size_t)v * MLP_N)) + lane;
                if (ci == 0) {                       // warp-uniform
                    __stcs(dst, zero4);              // streaming zero
                    continue;
                }
                const int npt = ci < CAP ? ci : CAP;
                unsigned long long vmax01 = pack2(-1e30f, -1e30f);
                unsigned long long vmax23 = vmax01;

                for (int k = 0; k < npt; ++k) {
                    const int pt = (k == 0) ? __shfl_sync(FULLM, p, i)
                                            : __ldg(&d_pidx[(size_t)v * CAP + k]);
                    const float x = xyz[pt * 3 + 0];
                    const float y = xyz[pt * 3 + 1];
                    const float z = xyz[pt * 3 + 2];
                    const float dx = x - floorf(x / 0.32f) * 0.32f;
                    const float dy = y - floorf(y / 0.32f) * 0.32f;
                    const float dz = z - floorf(z / 6.0f) * 6.0f;

                    const float4* f4 = (const float4*)(pfeat + (size_t)pt * D_IN);
                    const float4 fa = f4[0], fb = f4[1], fc = f4[2], fd = f4[3];
                    const float vin[D_TOT] = {
                        fa.x, fa.y, fa.z, fa.w,
                        fb.x, fb.y, fb.z, fb.w,
                        fc.x, fc.y, fc.z, fc.w,
                        fd.x, fd.y, fd.z, fd.w,
                        dx, dy, dz
                    };
                    unsigned long long acc01 = b01, acc23 = b23;
                    #pragma unroll
                    for (int d = 0; d < D_TOT; ++d) {
                        const ulonglong2 wp =
                            *(const ulonglong2*)(sW4 + d * (MLP_N / 4) + lane);
                        const unsigned long long vv = dup2(vin[d]);
                        acc01 = fma2(vv, wp.x, acc01);
                        acc23 = fma2(vv, wp.y, acc23);
                    }
                    float a0, a1, a2, a3, m0, m1, m2, m3;
                    unpack2(acc01, a0, a1); unpack2(acc23, a2, a3);
                    unpack2(vmax01, m0, m1); unpack2(vmax23, m2, m3);
                    vmax01 = pack2(fmaxf(m0, a0), fmaxf(m1, a1));
                    vmax23 = pack2(fmaxf(m2, a2), fmaxf(m3, a3));
                }

                float m0, m1, m2, m3;
                unpack2(vmax01, m0, m1);
                unpack2(vmax23, m2, m3);
                // relu monotone: max-then-relu == max-of-relus
                __stcs(dst, make_float4(fmaxf(m0, 0.f), fmaxf(m1, 0.f),
                                        fmaxf(m2, 0.f), fmaxf(m3, 0.f)));
            }

            if (half == 0 && c1 > 0) {
                // p1 (issued at loop head) has landed; prefetch its data now,
                // ~500 cycles before the next chunk begins using it.
                prefetchL1(xyz + (size_t)p1 * 3);
                prefetchL1(pfeat + (size_t)p1 * D_IN);
            }
        }

        c = c1; c1 = c2; p = p1;
    }
}

extern "C" void kernel_launch(void* const* d_in, const int* in_sizes, int n_in,
                              void* d_out, int out_size)
{
    const float*        xyz   = (const float*)d_in[0];
    const float*        pfeat = (const float*)d_in[1];
    const unsigned int* mask  = (const unsigned int*)d_in[2];
    const float*        W     = (const float*)d_in[3];
    const float*        bias  = (const float*)d_in[4];
    float*              out   = (float*)d_out;

    // d_cnt starts zeroed (static init) and is re-zeroed by gather_kernel each call.
    bin_points_kernel<<<(TOTAL + 255) / 256, 256>>>(xyz, mask);
    gather_kernel<<<BLOCKS, THREADS>>>(xyz, pfeat, W, bias, out);
}